// round 8
// baseline (speedup 1.0000x reference)
#include <cuda_runtime.h>
#include <math.h>

#define NCOMP 20

// 4 events per warp, 8 lanes per event. 3-round 8-ary search over sorted rows.
// Embeddings gathered as float4 (2 LDG/warp); t_last taken from round-3
// registers, edge case covered by an already-probed (L1-hot) scalar.
__global__ void __launch_bounds__(256) markov_kernel(
        const int* __restrict__ src,
        const int* __restrict__ dst,
        const float* __restrict__ t,
        const float* __restrict__ x_pad,
        const float* __restrict__ t_pad,
        const float* __restrict__ emb_src,
        const float* __restrict__ emb_dst,
        const float* __restrict__ alpha_p,
        const float* __restrict__ beta_p,
        float* __restrict__ out,
        int E, int L)
{
    const int lane = threadIdx.x & 31;
    const int sub  = lane >> 3;       // event slot within warp (0..3)
    const int sl   = lane & 7;        // sublane within event (0..7)
    const int warp = (blockIdx.x * blockDim.x + threadIdx.x) >> 5;
    const int e = warp * 4 + sub;     // E == grid*events_per_block exactly

    const float tq = __ldg(&t[e]);
    const float* __restrict__ rowT = t_pad + (size_t)e * L;
    const float* __restrict__ rowX = x_pad + (size_t)e * L;

    // ---- embeddings: 20 floats = 5 float4 per table, lanes 0..4 ----
    const int s = __ldg(&src[e]);
    const int d = __ldg(&dst[e]);
    float prod = 0.0f;
    if (sl < 5) {
        const float4 ea = __ldg((const float4*)(emb_src + (size_t)s * NCOMP) + sl);
        const float4 eb = __ldg((const float4*)(emb_dst + (size_t)d * NCOMP) + sl);
        prod = ea.x * eb.x + ea.y * eb.y + ea.z * eb.z + ea.w * eb.w;
    }

    const int shift = sub * 8;

    // ---- round 1: 8 chunks of 256; probe each chunk's last element ----
    float v1 = __ldg(&rowT[(sl + 1) * 256 - 1]);
    unsigned bb = __ballot_sync(0xffffffffu, v1 < tq);
    const int c1i = min(__popc((bb >> shift) & 0xffu), 7);

    // ---- round 2: 8 sub-chunks of 32 within chunk c1i ----
    const int base1 = c1i * 256;
    float v2 = __ldg(&rowT[base1 + (sl + 1) * 32 - 1]);
    bb = __ballot_sync(0xffffffffu, v2 < tq);
    const int c2i = min(__popc((bb >> shift) & 0xffu), 7);

    const int base2 = base1 + c2i * 32;

    // ---- round 3: 32-float sub-chunk, float4/lane (coalesced 128 B) ----
    const float4 q = *reinterpret_cast<const float4*>(rowT + base2 + sl * 4);
    // edge scalar rowT[base2-1]: same line as a round-1/2 probe -> L1 hit
    const float t_m = __ldg(&rowT[max(base2 - 1, 0)]);

    int loc = (q.x < tq) + (q.y < tq) + (q.z < tq) + (q.w < tq);

    // ---- fused 8-lane segment reduction: local count + embedding dot ----
    #pragma unroll
    for (int off = 1; off < 8; off <<= 1) {
        loc  += __shfl_xor_sync(0xffffffffu, loc, off);
        prod += __shfl_xor_sync(0xffffffffu, prod, off);
    }
    // loc, prod uniform within each 8-lane group

    const int cnt = base2 + loc;           // full-below path yields L correctly

    // ---- t_last: from round-3 registers or the pre-probed edge scalar ----
    float t_last;
    if (loc > 0) {
        const int o  = loc - 1;
        const int ls = o >> 2;
        const int cp = o & 3;
        float tsel = (cp == 0) ? q.x : (cp == 1) ? q.y : (cp == 2) ? q.z : q.w;
        t_last = __shfl_sync(0xffffffffu, tsel, shift + ls);
    } else {
        t_last = t_m;                      // idx == base2-1 (or cnt==0, unused)
    }

    if (sl == 0) {
        float dot = prod;
        float base = fmaxf(dot, 0.0f) + log1pf(expf(-fabsf(dot)));  // softplus

        float incr = 0.0f;
        if (cnt > 0) {
            const float x_raw = __ldg(&rowX[cnt - 1]);
            const float z = (x_raw - 0.5f) * 4.0f;    // (x-MEAN)/VAR, VAR=0.25
            const float sig = 1.0f / (1.0f + expf(-z));
            const float alpha = __ldg(alpha_p);
            const float beta  = __ldg(beta_p);
            incr = alpha * sig * expf(-beta * (tq - t_last));
        }
        out[e] = base + incr;
    }
}

extern "C" void kernel_launch(void* const* d_in, const int* in_sizes, int n_in,
                              void* d_out, int out_size)
{
    const int*   src     = (const int*)  d_in[0];
    const int*   dst     = (const int*)  d_in[1];
    const float* t       = (const float*)d_in[2];
    const float* x_pad   = (const float*)d_in[3];
    const float* t_pad   = (const float*)d_in[4];
    const float* emb_src = (const float*)d_in[5];
    const float* emb_dst = (const float*)d_in[6];
    const float* alpha   = (const float*)d_in[7];
    const float* beta    = (const float*)d_in[8];
    float* out = (float*)d_out;

    const int E = in_sizes[2];
    const int L = in_sizes[4] / E;     // 2048

    // 4 events per warp; 256 threads = 8 warps = 32 events/block -> 512 blocks
    const int threads = 256;
    const int events_per_block = 32;
    const int blocks = (E + events_per_block - 1) / events_per_block;
    markov_kernel<<<blocks, threads>>>(src, dst, t, x_pad, t_pad,
                                       emb_src, emb_dst, alpha, beta,
                                       out, E, L);
}

// round 9
// speedup vs baseline: 1.0258x; 1.0258x over previous
#include <cuda_runtime.h>
#include <math.h>

#define NCOMP 20

// 2 events per warp, 16 lanes per event. Same 3-round 8-ary search and identical
// memory-line footprint as the 6.7us champion; redundant probes coalesce in L1.
// Doubles warp count (8192) to raise occupancy / latency hiding.
__global__ void __launch_bounds__(256) markov_kernel(
        const int* __restrict__ src,
        const int* __restrict__ dst,
        const float* __restrict__ t,
        const float* __restrict__ x_pad,
        const float* __restrict__ t_pad,
        const float* __restrict__ emb_src,
        const float* __restrict__ emb_dst,
        const float* __restrict__ alpha_p,
        const float* __restrict__ beta_p,
        float* __restrict__ out,
        int E, int L)
{
    const int lane = threadIdx.x & 31;
    const int sub  = lane >> 4;          // event slot within warp (0..1)
    const int sl   = lane & 15;          // sublane within event (0..15)
    const int sl8  = sl & 7;             // probe lane (two halves redundant)
    const int warp = (blockIdx.x * blockDim.x + threadIdx.x) >> 5;
    const int e = warp * 2 + sub;
    if (e >= E) return;

    const float tq = __ldg(&t[e]);
    const float* __restrict__ rowT = t_pad + (size_t)e * L;
    const float* __restrict__ rowX = x_pad + (size_t)e * L;

    // ---- embeddings: scalar gathers on 16 lanes (sl 0..15 + sl<4 for 16..19) ----
    const int s = __ldg(&src[e]);
    const int d = __ldg(&dst[e]);
    const float* es = emb_src + (size_t)s * NCOMP;
    const float* ed = emb_dst + (size_t)d * NCOMP;
    float a0 = __ldg(&es[sl]), b0 = __ldg(&ed[sl]);
    float a1 = 0.0f, b1 = 0.0f;
    if (sl < 4) { a1 = __ldg(&es[sl + 16]); b1 = __ldg(&ed[sl + 16]); }

    const int shift = sub * 16;

    // ---- round 1: 8 chunks of 256; both 8-lane halves probe the same addresses ----
    float v1 = __ldg(&rowT[(sl8 + 1) * 256 - 1]);
    unsigned bb = __ballot_sync(0xffffffffu, v1 < tq);
    const int c1i = min(__popc((bb >> shift) & 0xffu), 7);   // lower-half bits only

    // ---- round 2: 8 sub-chunks of 32 within chunk c1i (redundant halves) ----
    const int base1 = c1i * 256;
    float v2 = __ldg(&rowT[base1 + (sl8 + 1) * 32 - 1]);
    bb = __ballot_sync(0xffffffffu, v2 < tq);
    const int c2i = min(__popc((bb >> shift) & 0xffu), 7);

    const int base2 = base1 + c2i * 32;

    // ---- round 3: 32-float sub-chunk, float2 per lane (coalesced 128 B) ----
    const float2 p = *reinterpret_cast<const float2*>(rowT + base2 + sl * 2);
    int loc = (p.x < tq) + (p.y < tq);

    // ---- fused 16-lane segment reduction: local count + embedding dot ----
    float prod = a0 * b0 + a1 * b1;
    #pragma unroll
    for (int off = 1; off < 16; off <<= 1) {
        loc  += __shfl_xor_sync(0xffffffffu, loc, off);
        prod += __shfl_xor_sync(0xffffffffu, prod, off);
    }
    // loc, prod uniform within each 16-lane group

    const int cnt = base2 + loc;          // clamped path yields 2048 correctly
    const bool has_prev = (cnt > 0);
    const int idx = has_prev ? (cnt - 1) : 0;

    if (sl == 0) {
        float dot = prod;
        float base = fmaxf(dot, 0.0f) + log1pf(expf(-fabsf(dot)));  // softplus

        float incr = 0.0f;
        if (has_prev) {
            // idx's line is always L1-hot: base2..base2+31 just loaded in r3;
            // base2-1 is exactly a round-1/round-2 probe address.
            const float t_last = __ldg(&rowT[idx]);
            const float x_raw  = __ldg(&rowX[idx]);
            const float z = (x_raw - 0.5f) * 4.0f;    // (x-MEAN)/VAR, VAR=0.25
            const float sig = 1.0f / (1.0f + expf(-z));
            const float alpha = __ldg(alpha_p);
            const float beta  = __ldg(beta_p);
            incr = alpha * sig * expf(-beta * (tq - t_last));
        }
        out[e] = base + incr;
    }
}

extern "C" void kernel_launch(void* const* d_in, const int* in_sizes, int n_in,
                              void* d_out, int out_size)
{
    const int*   src     = (const int*)  d_in[0];
    const int*   dst     = (const int*)  d_in[1];
    const float* t       = (const float*)d_in[2];
    const float* x_pad   = (const float*)d_in[3];
    const float* t_pad   = (const float*)d_in[4];
    const float* emb_src = (const float*)d_in[5];
    const float* emb_dst = (const float*)d_in[6];
    const float* alpha   = (const float*)d_in[7];
    const float* beta    = (const float*)d_in[8];
    float* out = (float*)d_out;

    const int E = in_sizes[2];
    const int L = in_sizes[4] / E;     // 2048

    // 2 events per warp; 256 threads = 8 warps = 16 events/block -> 1024 blocks
    const int threads = 256;
    const int events_per_block = 16;
    const int blocks = (E + events_per_block - 1) / events_per_block;
    markov_kernel<<<blocks, threads>>>(src, dst, t, x_pad, t_pad,
                                       emb_src, emb_dst, alpha, beta,
                                       out, E, L);
}